// round 9
// baseline (speedup 1.0000x reference)
#include <cuda_runtime.h>

#define D_FEAT 64

__device__ int g_row_ptr[100001];

// Kernel A: boundary scatter (row sorted): thread i writes CSR starts for rows
// beginning at edge i, covering empty rows; thread E closes the tail.
__global__ void build_row_ptr_scatter(const int* __restrict__ row, int n, int E) {
    int i = blockIdx.x * blockDim.x + threadIdx.x;
    if (i > E) return;
    if (i == 0) {
        int r0 = __ldg(&row[0]);
        for (int r = 0; r <= r0; r++) g_row_ptr[r] = 0;
    } else if (i == E) {
        int rp = __ldg(&row[E - 1]);
        for (int r = rp + 1; r <= n; r++) g_row_ptr[r] = E;
    } else {
        int rc = __ldg(&row[i]);
        int rp = __ldg(&row[i - 1]);
        for (int r = rp + 1; r <= rc; r++) g_row_ptr[r] = i;
    }
}

// Kernel B: one warp per row, lane owns features {2l,2l+1} (float2).
// SINGLE predicated 8-edge batch loop: every row is ceil(deg/8) uniform
// batches with 8 gathers in flight; no 4-batch, no serial scalar tail.
// Inactive slots clamp to the last edge (same cache lines) with v=0.
__global__ void __launch_bounds__(64)
spmm_mean_warp_per_row(const float* __restrict__ x,
                       const float* __restrict__ vals,
                       const int* __restrict__ col,
                       float* __restrict__ out,
                       int n) {
    int warp_id = (blockIdx.x * blockDim.x + threadIdx.x) >> 5;
    int lane = threadIdx.x & 31;
    if (warp_id >= n) return;

    int s = g_row_ptr[warp_id];
    int e = g_row_ptr[warp_id + 1];

    const float* xb = x + 2 * lane;
    float2 a0 = make_float2(0.f, 0.f);
    float2 a1 = make_float2(0.f, 0.f);

    int last = e - 1;  // valid whenever the loop body runs (e > s)

    for (int i = s; i < e; i += 8) {
        int i0 = i + 0 < e ? i + 0 : last;
        int i1 = i + 1 < e ? i + 1 : last;
        int i2 = i + 2 < e ? i + 2 : last;
        int i3 = i + 3 < e ? i + 3 : last;
        int i4 = i + 4 < e ? i + 4 : last;
        int i5 = i + 5 < e ? i + 5 : last;
        int i6 = i + 6 < e ? i + 6 : last;
        int i7 = i + 7 < e ? i + 7 : last;

        int c0 = __ldg(&col[i0]);
        int c1 = __ldg(&col[i1]);
        int c2 = __ldg(&col[i2]);
        int c3 = __ldg(&col[i3]);
        int c4 = __ldg(&col[i4]);
        int c5 = __ldg(&col[i5]);
        int c6 = __ldg(&col[i6]);
        int c7 = __ldg(&col[i7]);

        float2 x0 = __ldg(reinterpret_cast<const float2*>(xb + (size_t)c0 * D_FEAT));
        float2 x1 = __ldg(reinterpret_cast<const float2*>(xb + (size_t)c1 * D_FEAT));
        float2 x2 = __ldg(reinterpret_cast<const float2*>(xb + (size_t)c2 * D_FEAT));
        float2 x3 = __ldg(reinterpret_cast<const float2*>(xb + (size_t)c3 * D_FEAT));
        float2 x4 = __ldg(reinterpret_cast<const float2*>(xb + (size_t)c4 * D_FEAT));
        float2 x5 = __ldg(reinterpret_cast<const float2*>(xb + (size_t)c5 * D_FEAT));
        float2 x6 = __ldg(reinterpret_cast<const float2*>(xb + (size_t)c6 * D_FEAT));
        float2 x7 = __ldg(reinterpret_cast<const float2*>(xb + (size_t)c7 * D_FEAT));

        float v0 = (i + 0 < e) ? __ldg(&vals[i0]) : 0.f;
        float v1 = (i + 1 < e) ? __ldg(&vals[i1]) : 0.f;
        float v2 = (i + 2 < e) ? __ldg(&vals[i2]) : 0.f;
        float v3 = (i + 3 < e) ? __ldg(&vals[i3]) : 0.f;
        float v4 = (i + 4 < e) ? __ldg(&vals[i4]) : 0.f;
        float v5 = (i + 5 < e) ? __ldg(&vals[i5]) : 0.f;
        float v6 = (i + 6 < e) ? __ldg(&vals[i6]) : 0.f;
        float v7 = (i + 7 < e) ? __ldg(&vals[i7]) : 0.f;

        a0.x = fmaf(v0, x0.x, a0.x); a0.y = fmaf(v0, x0.y, a0.y);
        a1.x = fmaf(v1, x1.x, a1.x); a1.y = fmaf(v1, x1.y, a1.y);
        a0.x = fmaf(v2, x2.x, a0.x); a0.y = fmaf(v2, x2.y, a0.y);
        a1.x = fmaf(v3, x3.x, a1.x); a1.y = fmaf(v3, x3.y, a1.y);
        a0.x = fmaf(v4, x4.x, a0.x); a0.y = fmaf(v4, x4.y, a0.y);
        a1.x = fmaf(v5, x5.x, a1.x); a1.y = fmaf(v5, x5.y, a1.y);
        a0.x = fmaf(v6, x6.x, a0.x); a0.y = fmaf(v6, x6.y, a0.y);
        a1.x = fmaf(v7, x7.x, a1.x); a1.y = fmaf(v7, x7.y, a1.y);
    }

    int deg = e - s;
    float inv = 1.0f / (float)(deg > 0 ? deg : 1);
    float2 o = make_float2((a0.x + a1.x) * inv, (a0.y + a1.y) * inv);

    *reinterpret_cast<float2*>(&out[(size_t)warp_id * D_FEAT + 2 * lane]) = o;
}

extern "C" void kernel_launch(void* const* d_in, const int* in_sizes, int n_in,
                              void* d_out, int out_size) {
    const float* x    = (const float*)d_in[0];
    const float* vals = (const float*)d_in[1];
    const int*   row  = (const int*)d_in[2];
    const int*   col  = (const int*)d_in[3];
    float* out = (float*)d_out;

    int n = in_sizes[0] / D_FEAT;   // 100000
    int E = in_sizes[1];            // 1200000

    {
        int threads = 256;
        int blocks = (E + 1 + threads - 1) / threads;
        build_row_ptr_scatter<<<blocks, threads>>>(row, n, E);
    }
    {
        int threads = 64;                    // 2 warps/block: straggler isolation
        int rows_per_block = threads / 32;
        int blocks = (n + rows_per_block - 1) / rows_per_block;
        spmm_mean_warp_per_row<<<blocks, threads>>>(x, vals, col, out, n);
    }
}

// round 10
// speedup vs baseline: 1.1645x; 1.1645x over previous
#include <cuda_runtime.h>

#define D_FEAT 64

__device__ int g_row_ptr[100001];

// Kernel A: boundary scatter (row sorted). shfl_up shares the neighbor value
// so each warp issues ~33 loads per 32 threads instead of 64.
__global__ void build_row_ptr_scatter(const int* __restrict__ row, int n, int E) {
    int i = blockIdx.x * blockDim.x + threadIdx.x;
    if (i > E) return;
    int lane = threadIdx.x & 31;

    int rc = (i < E) ? __ldg(&row[i]) : 0;       // row[i] (unused at i==E)
    int rp_shfl = __shfl_up_sync(0xffffffffu, rc, 1);

    if (i == 0) {
        for (int r = 0; r <= rc; r++) g_row_ptr[r] = 0;
    } else if (i == E) {
        int rp = __ldg(&row[E - 1]);
        for (int r = rp + 1; r <= n; r++) g_row_ptr[r] = E;
    } else {
        int rp = (lane == 0) ? __ldg(&row[i - 1]) : rp_shfl;
        for (int r = rp + 1; r <= rc; r++) g_row_ptr[r] = i;
    }
}

// Kernel B: one warp per row, lane owns features {2l,2l+1} (float2).
// 8-edge main loop (8 gathers in flight), 4-edge secondary, scalar tail.
// regs=32 -> full 64 warps/SM. 64-thread blocks for straggler isolation.
__global__ void __launch_bounds__(64)
spmm_mean_warp_per_row(const float* __restrict__ x,
                       const float* __restrict__ vals,
                       const int* __restrict__ col,
                       float* __restrict__ out,
                       int n) {
    int warp_id = (blockIdx.x * blockDim.x + threadIdx.x) >> 5;
    int lane = threadIdx.x & 31;
    if (warp_id >= n) return;

    int s = g_row_ptr[warp_id];
    int e = g_row_ptr[warp_id + 1];

    const float* xb = x + 2 * lane;
    float2 a0 = make_float2(0.f, 0.f);
    float2 a1 = make_float2(0.f, 0.f);

    int i = s;

    // Main loop: 8 edges; cols issued first so gathers launch ASAP.
    for (; i + 8 <= e; i += 8) {
        int c0 = __ldg(&col[i + 0]);
        int c1 = __ldg(&col[i + 1]);
        int c2 = __ldg(&col[i + 2]);
        int c3 = __ldg(&col[i + 3]);
        int c4 = __ldg(&col[i + 4]);
        int c5 = __ldg(&col[i + 5]);
        int c6 = __ldg(&col[i + 6]);
        int c7 = __ldg(&col[i + 7]);
        float2 x0 = __ldg(reinterpret_cast<const float2*>(xb + (size_t)c0 * D_FEAT));
        float2 x1 = __ldg(reinterpret_cast<const float2*>(xb + (size_t)c1 * D_FEAT));
        float2 x2 = __ldg(reinterpret_cast<const float2*>(xb + (size_t)c2 * D_FEAT));
        float2 x3 = __ldg(reinterpret_cast<const float2*>(xb + (size_t)c3 * D_FEAT));
        float2 x4 = __ldg(reinterpret_cast<const float2*>(xb + (size_t)c4 * D_FEAT));
        float2 x5 = __ldg(reinterpret_cast<const float2*>(xb + (size_t)c5 * D_FEAT));
        float2 x6 = __ldg(reinterpret_cast<const float2*>(xb + (size_t)c6 * D_FEAT));
        float2 x7 = __ldg(reinterpret_cast<const float2*>(xb + (size_t)c7 * D_FEAT));
        float v0 = __ldg(&vals[i + 0]);
        float v1 = __ldg(&vals[i + 1]);
        float v2 = __ldg(&vals[i + 2]);
        float v3 = __ldg(&vals[i + 3]);
        float v4 = __ldg(&vals[i + 4]);
        float v5 = __ldg(&vals[i + 5]);
        float v6 = __ldg(&vals[i + 6]);
        float v7 = __ldg(&vals[i + 7]);
        a0.x = fmaf(v0, x0.x, a0.x); a0.y = fmaf(v0, x0.y, a0.y);
        a1.x = fmaf(v1, x1.x, a1.x); a1.y = fmaf(v1, x1.y, a1.y);
        a0.x = fmaf(v2, x2.x, a0.x); a0.y = fmaf(v2, x2.y, a0.y);
        a1.x = fmaf(v3, x3.x, a1.x); a1.y = fmaf(v3, x3.y, a1.y);
        a0.x = fmaf(v4, x4.x, a0.x); a0.y = fmaf(v4, x4.y, a0.y);
        a1.x = fmaf(v5, x5.x, a1.x); a1.y = fmaf(v5, x5.y, a1.y);
        a0.x = fmaf(v6, x6.x, a0.x); a0.y = fmaf(v6, x6.y, a0.y);
        a1.x = fmaf(v7, x7.x, a1.x); a1.y = fmaf(v7, x7.y, a1.y);
    }

    // Secondary: 4 edges.
    for (; i + 4 <= e; i += 4) {
        int c0 = __ldg(&col[i + 0]);
        int c1 = __ldg(&col[i + 1]);
        int c2 = __ldg(&col[i + 2]);
        int c3 = __ldg(&col[i + 3]);
        float2 x0 = __ldg(reinterpret_cast<const float2*>(xb + (size_t)c0 * D_FEAT));
        float2 x1 = __ldg(reinterpret_cast<const float2*>(xb + (size_t)c1 * D_FEAT));
        float2 x2 = __ldg(reinterpret_cast<const float2*>(xb + (size_t)c2 * D_FEAT));
        float2 x3 = __ldg(reinterpret_cast<const float2*>(xb + (size_t)c3 * D_FEAT));
        float v0 = __ldg(&vals[i + 0]);
        float v1 = __ldg(&vals[i + 1]);
        float v2 = __ldg(&vals[i + 2]);
        float v3 = __ldg(&vals[i + 3]);
        a0.x = fmaf(v0, x0.x, a0.x); a0.y = fmaf(v0, x0.y, a0.y);
        a1.x = fmaf(v1, x1.x, a1.x); a1.y = fmaf(v1, x1.y, a1.y);
        a0.x = fmaf(v2, x2.x, a0.x); a0.y = fmaf(v2, x2.y, a0.y);
        a1.x = fmaf(v3, x3.x, a1.x); a1.y = fmaf(v3, x3.y, a1.y);
    }

    // Tail: <=3 scalar edges.
    for (; i < e; i++) {
        int   c = __ldg(&col[i]);
        float v = __ldg(&vals[i]);
        float2 xv = __ldg(reinterpret_cast<const float2*>(xb + (size_t)c * D_FEAT));
        a0.x = fmaf(v, xv.x, a0.x);
        a0.y = fmaf(v, xv.y, a0.y);
    }

    int deg = e - s;
    float inv = 1.0f / (float)(deg > 0 ? deg : 1);
    float2 o = make_float2((a0.x + a1.x) * inv, (a0.y + a1.y) * inv);

    *reinterpret_cast<float2*>(&out[(size_t)warp_id * D_FEAT + 2 * lane]) = o;
}

extern "C" void kernel_launch(void* const* d_in, const int* in_sizes, int n_in,
                              void* d_out, int out_size) {
    const float* x    = (const float*)d_in[0];
    const float* vals = (const float*)d_in[1];
    const int*   row  = (const int*)d_in[2];
    const int*   col  = (const int*)d_in[3];
    float* out = (float*)d_out;

    int n = in_sizes[0] / D_FEAT;   // 100000
    int E = in_sizes[1];            // 1200000

    {
        int threads = 256;
        int blocks = (E + 1 + threads - 1) / threads;
        build_row_ptr_scatter<<<blocks, threads>>>(row, n, E);
    }
    {
        int threads = 64;                    // 2 warps/block
        int rows_per_block = threads / 32;
        int blocks = (n + rows_per_block - 1) / rows_per_block;
        spmm_mean_warp_per_row<<<blocks, threads>>>(x, vals, col, out, n);
    }
}

// round 11
// speedup vs baseline: 1.2221x; 1.0495x over previous
#include <cuda_runtime.h>

#define D_FEAT 64

__device__ int g_row_ptr[100001];

// L2-only cached load (bypass L1 fill) for the x-gathers.
__device__ __forceinline__ float2 ldcg_f2(const float2* p) {
    float2 r;
    asm volatile("ld.global.cg.v2.f32 {%0, %1}, [%2];"
                 : "=f"(r.x), "=f"(r.y) : "l"(p));
    return r;
}

// Kernel A: boundary scatter (row sorted). shfl_up shares the neighbor value.
__global__ void build_row_ptr_scatter(const int* __restrict__ row, int n, int E) {
    int i = blockIdx.x * blockDim.x + threadIdx.x;
    if (i > E) return;
    int lane = threadIdx.x & 31;

    int rc = (i < E) ? __ldg(&row[i]) : 0;
    int rp_shfl = __shfl_up_sync(0xffffffffu, rc, 1);

    if (i == 0) {
        for (int r = 0; r <= rc; r++) g_row_ptr[r] = 0;
    } else if (i == E) {
        int rp = __ldg(&row[E - 1]);
        for (int r = rp + 1; r <= n; r++) g_row_ptr[r] = E;
    } else {
        int rp = (lane == 0) ? __ldg(&row[i - 1]) : rp_shfl;
        for (int r = rp + 1; r <= rc; r++) g_row_ptr[r] = i;
    }
}

// Kernel B: one warp per row, lane owns features {2l,2l+1} (float2).
// 8-edge main loop, 4-edge secondary, scalar tail. regs=32 -> 64 warps/SM.
// x-gathers use .cg (L2-only): ~1% L1 hit rate makes L1 fill pure overhead
// and it evicts the metadata stream that DOES reuse L1.
__global__ void __launch_bounds__(128)
spmm_mean_warp_per_row(const float* __restrict__ x,
                       const float* __restrict__ vals,
                       const int* __restrict__ col,
                       float* __restrict__ out,
                       int n) {
    int warp_id = (blockIdx.x * blockDim.x + threadIdx.x) >> 5;
    int lane = threadIdx.x & 31;
    if (warp_id >= n) return;

    int s = g_row_ptr[warp_id];
    int e = g_row_ptr[warp_id + 1];

    const float* xb = x + 2 * lane;
    float2 a0 = make_float2(0.f, 0.f);
    float2 a1 = make_float2(0.f, 0.f);

    int i = s;

    // Main loop: 8 edges; cols issued first so gathers launch ASAP.
    for (; i + 8 <= e; i += 8) {
        int c0 = __ldg(&col[i + 0]);
        int c1 = __ldg(&col[i + 1]);
        int c2 = __ldg(&col[i + 2]);
        int c3 = __ldg(&col[i + 3]);
        int c4 = __ldg(&col[i + 4]);
        int c5 = __ldg(&col[i + 5]);
        int c6 = __ldg(&col[i + 6]);
        int c7 = __ldg(&col[i + 7]);
        float2 x0 = ldcg_f2(reinterpret_cast<const float2*>(xb + (size_t)c0 * D_FEAT));
        float2 x1 = ldcg_f2(reinterpret_cast<const float2*>(xb + (size_t)c1 * D_FEAT));
        float2 x2 = ldcg_f2(reinterpret_cast<const float2*>(xb + (size_t)c2 * D_FEAT));
        float2 x3 = ldcg_f2(reinterpret_cast<const float2*>(xb + (size_t)c3 * D_FEAT));
        float2 x4 = ldcg_f2(reinterpret_cast<const float2*>(xb + (size_t)c4 * D_FEAT));
        float2 x5 = ldcg_f2(reinterpret_cast<const float2*>(xb + (size_t)c5 * D_FEAT));
        float2 x6 = ldcg_f2(reinterpret_cast<const float2*>(xb + (size_t)c6 * D_FEAT));
        float2 x7 = ldcg_f2(reinterpret_cast<const float2*>(xb + (size_t)c7 * D_FEAT));
        float v0 = __ldg(&vals[i + 0]);
        float v1 = __ldg(&vals[i + 1]);
        float v2 = __ldg(&vals[i + 2]);
        float v3 = __ldg(&vals[i + 3]);
        float v4 = __ldg(&vals[i + 4]);
        float v5 = __ldg(&vals[i + 5]);
        float v6 = __ldg(&vals[i + 6]);
        float v7 = __ldg(&vals[i + 7]);
        a0.x = fmaf(v0, x0.x, a0.x); a0.y = fmaf(v0, x0.y, a0.y);
        a1.x = fmaf(v1, x1.x, a1.x); a1.y = fmaf(v1, x1.y, a1.y);
        a0.x = fmaf(v2, x2.x, a0.x); a0.y = fmaf(v2, x2.y, a0.y);
        a1.x = fmaf(v3, x3.x, a1.x); a1.y = fmaf(v3, x3.y, a1.y);
        a0.x = fmaf(v4, x4.x, a0.x); a0.y = fmaf(v4, x4.y, a0.y);
        a1.x = fmaf(v5, x5.x, a1.x); a1.y = fmaf(v5, x5.y, a1.y);
        a0.x = fmaf(v6, x6.x, a0.x); a0.y = fmaf(v6, x6.y, a0.y);
        a1.x = fmaf(v7, x7.x, a1.x); a1.y = fmaf(v7, x7.y, a1.y);
    }

    // Secondary: 4 edges.
    for (; i + 4 <= e; i += 4) {
        int c0 = __ldg(&col[i + 0]);
        int c1 = __ldg(&col[i + 1]);
        int c2 = __ldg(&col[i + 2]);
        int c3 = __ldg(&col[i + 3]);
        float2 x0 = ldcg_f2(reinterpret_cast<const float2*>(xb + (size_t)c0 * D_FEAT));
        float2 x1 = ldcg_f2(reinterpret_cast<const float2*>(xb + (size_t)c1 * D_FEAT));
        float2 x2 = ldcg_f2(reinterpret_cast<const float2*>(xb + (size_t)c2 * D_FEAT));
        float2 x3 = ldcg_f2(reinterpret_cast<const float2*>(xb + (size_t)c3 * D_FEAT));
        float v0 = __ldg(&vals[i + 0]);
        float v1 = __ldg(&vals[i + 1]);
        float v2 = __ldg(&vals[i + 2]);
        float v3 = __ldg(&vals[i + 3]);
        a0.x = fmaf(v0, x0.x, a0.x); a0.y = fmaf(v0, x0.y, a0.y);
        a1.x = fmaf(v1, x1.x, a1.x); a1.y = fmaf(v1, x1.y, a1.y);
        a0.x = fmaf(v2, x2.x, a0.x); a0.y = fmaf(v2, x2.y, a0.y);
        a1.x = fmaf(v3, x3.x, a1.x); a1.y = fmaf(v3, x3.y, a1.y);
    }

    // Tail: <=3 scalar edges.
    for (; i < e; i++) {
        int   c = __ldg(&col[i]);
        float v = __ldg(&vals[i]);
        float2 xv = ldcg_f2(reinterpret_cast<const float2*>(xb + (size_t)c * D_FEAT));
        a0.x = fmaf(v, xv.x, a0.x);
        a0.y = fmaf(v, xv.y, a0.y);
    }

    int deg = e - s;
    float inv = 1.0f / (float)(deg > 0 ? deg : 1);
    float2 o = make_float2((a0.x + a1.x) * inv, (a0.y + a1.y) * inv);

    *reinterpret_cast<float2*>(&out[(size_t)warp_id * D_FEAT + 2 * lane]) = o;
}

extern "C" void kernel_launch(void* const* d_in, const int* in_sizes, int n_in,
                              void* d_out, int out_size) {
    const float* x    = (const float*)d_in[0];
    const float* vals = (const float*)d_in[1];
    const int*   row  = (const int*)d_in[2];
    const int*   col  = (const int*)d_in[3];
    float* out = (float*)d_out;

    int n = in_sizes[0] / D_FEAT;   // 100000
    int E = in_sizes[1];            // 1200000

    {
        int threads = 256;
        int blocks = (E + 1 + threads - 1) / threads;
        build_row_ptr_scatter<<<blocks, threads>>>(row, n, E);
    }
    {
        int threads = 128;                   // 4 warps/block (R8-verified best total)
        int rows_per_block = threads / 32;
        int blocks = (n + rows_per_block - 1) / rows_per_block;
        spmm_mean_warp_per_row<<<blocks, threads>>>(x, vals, col, out, n);
    }
}